// round 15
// baseline (speedup 1.0000x reference)
#include <cuda_runtime.h>
#include <cuda_fp16.h>
#include <math.h>
#include <stdint.h>

#define BB   32
#define DD   768
#define LL   12
#define HID  3072
#define NP   256
#define TT   8192
#define BHH  384

typedef __half fp16;

// ---------------- scratch (static device allocations) ----------------
__device__ float g_tok [TT*DD];
__device__ float g_ada [LL*BB*6*DD];
__device__ float g_adaf[BB*2*DD];
// fp16 activations
__device__ fp16 g_hmod[TT*DD];
__device__ fp16 g_qkv[(size_t)TT*3*DD];
__device__ fp16 g_oo[TT*DD];
__device__ fp16 g_hmid[(size_t)TT*HID];
__device__ fp16 g_c0 [32*DD];
__device__ fp16 g_tmid[(size_t)32*HID];
__device__ fp16 g_sc [32*DD];
// transposed fp16 weights [N][K]
__device__ fp16 g_qkvwT[(size_t)LL*3*DD*DD];
__device__ fp16 g_owT [(size_t)LL*DD*DD];
__device__ fp16 g_m1wT[(size_t)LL*HID*DD];
__device__ fp16 g_m2wT[(size_t)LL*DD*HID];
__device__ fp16 g_awT [(size_t)LL*6*DD*DD];
__device__ fp16 g_tw1T[(size_t)HID*DD];
__device__ fp16 g_tw2T[(size_t)DD*HID];
__device__ fp16 g_fawT[(size_t)2*DD*DD];

// ---------------- helpers ----------------
__device__ __forceinline__ uint32_t sm32(const void* p){
    uint32_t a;
    asm("{ .reg .u64 t; cvta.to.shared.u64 t, %1; cvt.u32.u64 %0, t; }" : "=r"(a) : "l"(p));
    return a;
}
__device__ __forceinline__ void cp16(uint32_t dst, const void* src){
    asm volatile("cp.async.cg.shared.global [%0], [%1], 16;" :: "r"(dst), "l"(src) : "memory");
}
__device__ __forceinline__ void ldsm4(uint32_t* r, uint32_t addr){
    asm volatile("ldmatrix.sync.aligned.m8n8.x4.shared.b16 {%0,%1,%2,%3}, [%4];"
        : "=r"(r[0]), "=r"(r[1]), "=r"(r[2]), "=r"(r[3]) : "r"(addr));
}
__device__ __forceinline__ void mmaf16(float* d, const uint32_t* a, uint32_t b0, uint32_t b1){
    asm volatile("mma.sync.aligned.m16n8k16.row.col.f32.f16.f16.f32 "
        "{%0,%1,%2,%3}, {%4,%5,%6,%7}, {%8,%9}, {%0,%1,%2,%3};"
        : "+f"(d[0]), "+f"(d[1]), "+f"(d[2]), "+f"(d[3])
        : "r"(a[0]), "r"(a[1]), "r"(a[2]), "r"(a[3]), "r"(b0), "r"(b1));
}
__device__ __forceinline__ uint32_t packh(fp16 a, fp16 b){
    return (uint32_t)__half_as_ushort(a) | ((uint32_t)__half_as_ushort(b) << 16);
}
__device__ __forceinline__ float gelu_f(float x){
    return 0.5f * x * (1.0f + erff(x * 0.7071067811865475f));
}
__device__ __forceinline__ float silu_f(float x){
    return x / (1.f + expf(-x));
}

// ---- fp16 K=64 chunk, row stride 144B
template<int MI>
__device__ __forceinline__ void mma64_chunk(uint32_t sb, int oA, int oB,
                                            int mrow0, int ncol0, int lane, float (*d)[4]){
    const int r8 = lane & 7, t1 = (lane >> 3) & 1, t2 = (lane >> 4) & 1;
#pragma unroll
    for (int ks = 0; ks < 4; ++ks){
        uint32_t a[MI][4], b[2][4];
        const int keA = ks*16 + t2*8;
        const int keB = ks*16 + t1*8;
#pragma unroll
        for (int mi = 0; mi < MI; ++mi)
            ldsm4(a[mi], sb + oA + (mrow0 + mi*16 + r8 + t1*8)*144 + keA*2);
#pragma unroll
        for (int p = 0; p < 2; ++p)
            ldsm4(b[p], sb + oB + (ncol0 + p*16 + r8 + t2*8)*144 + keB*2);
#pragma unroll
        for (int mi = 0; mi < MI; ++mi)
#pragma unroll
            for (int p = 0; p < 2; ++p){
                mmaf16(d[mi*4+p*2],   a[mi], b[p][0], b[p][1]);
                mmaf16(d[mi*4+p*2+1], a[mi], b[p][2], b[p][3]);
            }
    }
}

// ---------------- main GEMM: out[M,N] = A[M,K] @ W[N,K]^T ----------
// MTxNT CTA tile (MTx128 or 128x64 or 32x128), 8 warps, K=64 chunks, 3-stage.
// EPI: 0 fp32 | 1 gelu fp16 | 2 gated residual fp32 | 3 silu fp16 | 4 +cls fp32 |
//      5 fp16 | 6 (+cls then silu) fp16
template<int EPI, int MT, int NT>
__global__ void __launch_bounds__(256, 2) gemm_fp16(
    const fp16* __restrict__ A, int lda,
    const fp16* __restrict__ W,
    const float* __restrict__ bias,
    float* __restrict__ outF, fp16* __restrict__ outH,
    int Mvalid, int N, int K,
    const float* __restrict__ aux, int auxOff, const int* __restrict__ lab,
    long long wz, long long bz, long long oz)
{
    constexpr int MI   = (NT == 64) ? 2 : (MT / 32);
    constexpr int ASTG = MT * 144;
    constexpr int STGB = ASTG + NT * 144;
    extern __shared__ char smem[];
    const uint32_t sb = sm32(smem);
    const int tid = threadIdx.x, lane = tid & 31, wid = tid >> 5;
    const int warpM = (NT == 64) ? (wid & 3) : (wid & 1);
    const int warpN = (NT == 64) ? (wid >> 2) : (wid >> 1);
    const int m0 = blockIdx.y*MT, n0 = blockIdx.x*NT, z = blockIdx.z;
    const fp16* WZ = W + (size_t)z*wz;
    const float* BzP = bias + (size_t)z*bz;

    float d[MI*4][4];
#pragma unroll
    for (int i = 0; i < MI*4; ++i)
#pragma unroll
        for (int j = 0; j < 4; ++j) d[i][j] = 0.f;

    auto issue = [&](int s, int t){
        const int kt = t << 6;
        const uint32_t base = sb + s*STGB;
#pragma unroll
        for (int it = 0; it < MT/32; ++it){
            const int idx = tid + it*256;
            const int row = idx >> 3, q = idx & 7;
            cp16(base + row*144 + q*16, A + (size_t)(m0+row)*lda + kt + q*8);
        }
#pragma unroll
        for (int it = 0; it < NT/32; ++it){
            const int idx = tid + it*256;
            const int row = idx >> 3, q = idx & 7;
            cp16(base + ASTG + row*144 + q*16, WZ + (size_t)(n0+row)*K + kt + q*8);
        }
        asm volatile("cp.async.commit_group;" ::: "memory");
    };

    const int nk = K >> 6;
    issue(0, 0); issue(1, 1);
    for (int t = 0; t < nk; ++t){
        asm volatile("cp.async.wait_group 1;" ::: "memory");
        __syncthreads();
        if (t + 2 < nk) issue((t + 2) % 3, t + 2);
        else asm volatile("cp.async.commit_group;" ::: "memory");
        const int s = t % 3;
        mma64_chunk<MI>(sb + s*STGB, 0, ASTG, warpM*(MI*16), warpN*32, lane, d);
    }

    const int g = lane >> 2, tig = lane & 3;
#pragma unroll
    for (int mi = 0; mi < MI; ++mi){
#pragma unroll
        for (int ni = 0; ni < 4; ++ni){
            const int n = n0 + warpN*32 + ni*8 + tig*2;
            const float2 bv = *(const float2*)(BzP + n);
#pragma unroll
            for (int hr = 0; hr < 2; ++hr){
                const int m = m0 + warpM*(MI*16) + mi*16 + g + hr*8;
                if (m < Mvalid){
                    float x0 = d[mi*4+ni][hr*2+0] + bv.x;
                    float x1 = d[mi*4+ni][hr*2+1] + bv.y;
                    const size_t oi = (size_t)m*N + n;
                    if (EPI == 0){
                        *(float2*)(outF + (size_t)z*oz + oi) = make_float2(x0, x1);
                    } else if (EPI == 2){
                        const float2 gv = *(const float2*)(aux + (size_t)(m>>8)*(6*DD) + auxOff + n);
                        float2 ov = *(float2*)(outF + oi);
                        *(float2*)(outF + oi) = make_float2(ov.x + gv.x*x0, ov.y + gv.y*x1);
                    } else if (EPI == 4){
                        const float2 cv = *(const float2*)(aux + (size_t)lab[m]*DD + n);
                        *(float2*)(outF + oi) = make_float2(x0 + cv.x, x1 + cv.y);
                    } else if (EPI == 6){
                        const float2 cv = *(const float2*)(aux + (size_t)lab[m]*DD + n);
                        x0 = silu_f(x0 + cv.x); x1 = silu_f(x1 + cv.y);
                        *(uint32_t*)(outH + oi) = packh(__float2half_rn(x0), __float2half_rn(x1));
                    } else {
                        if (EPI == 1){ x0 = gelu_f(x0); x1 = gelu_f(x1); }
                        else if (EPI == 3){ x0 = silu_f(x0); x1 = silu_f(x1); }
                        *(uint32_t*)(outH + oi) = packh(__float2half_rn(x0), __float2half_rn(x1));
                    }
                }
            }
        }
    }
}
#define GSM128 (3*(128*144 + 128*144))
#define GSM64  (3*(128*144 + 64*144))
#define GSM32  (3*(32*144  + 128*144))

// ---------------- fused flash attention: O = softmax(QK^T/8) @ V ----------
// CTA: 128 query rows x all 256 keys; warp tile = 16 rows x 256 cols.
// smem: Q@0 (128x144), K@18432 (256x144), VT@55296 (64 rows x 528B). total 89088.
#define FA_SMEM 89088
__global__ void __launch_bounds__(256) fused_attn(const fp16* __restrict__ qkv,
                                                  fp16* __restrict__ oo){
    extern __shared__ char smem[];
    const uint32_t sb = sm32(smem);
    const int tid = threadIdx.x, lane = tid & 31, wid = tid >> 5;
    const int z = blockIdx.y, b = z/12, h = z%12;
    const int m0 = blockIdx.x*128;
    const size_t qbase = (size_t)b*NP*2304 + h*64;
    const size_t vbase = qbase + 1536;

    {
        const int lrow = tid >> 1, lq = tid & 1;
        const size_t qr = qbase + (size_t)(m0+lrow)*2304 + lq*32;
#pragma unroll
        for (int j = 0; j < 4; ++j)
            *(uint4*)(smem + lrow*144 + lq*64 + j*16) = *(const uint4*)(qkv + qr + j*8);
        const size_t kr = qbase + 768 + (size_t)tid*2304;
#pragma unroll
        for (int j = 0; j < 8; ++j)
            *(uint4*)(smem + 18432 + tid*144 + j*16) = *(const uint4*)(qkv + kr + j*8);
        const int vk = tid >> 3, vn8 = tid & 7;
#pragma unroll
        for (int it = 0; it < 8; ++it){
            const int k = it*32 + vk;
            const uint32_t* vv = (const uint32_t*)(qkv + vbase + (size_t)k*2304 + vn8*8);
#pragma unroll
            for (int w = 0; w < 4; ++w){
                const uint32_t pr = vv[w];
                const int dc = vn8*8 + w*2;
                *(fp16*)(smem + 55296 + dc*528 + k*2)     = __ushort_as_half((unsigned short)(pr & 0xffff));
                *(fp16*)(smem + 55296 + (dc+1)*528 + k*2) = __ushort_as_half((unsigned short)(pr >> 16));
            }
        }
    }
    __syncthreads();

    const int r8 = lane & 7, t1 = (lane >> 3) & 1, t2 = (lane >> 4) & 1;

    float d[32][4];
#pragma unroll
    for (int i = 0; i < 32; ++i)
#pragma unroll
        for (int j = 0; j < 4; ++j) d[i][j] = 0.f;

    const uint32_t qoff = sb + (wid*16 + r8 + t1*8)*144;
#pragma unroll
    for (int kc = 0; kc < 4; ++kc){
        uint32_t a[4];
        ldsm4(a, qoff + (kc*16 + t2*8)*2);
#pragma unroll
        for (int p = 0; p < 16; ++p){
            uint32_t bq[4];
            ldsm4(bq, sb + 18432 + (p*16 + r8 + t2*8)*144 + (kc*16 + t1*8)*2);
            mmaf16(d[p*2],   a, bq[0], bq[1]);
            mmaf16(d[p*2+1], a, bq[2], bq[3]);
        }
    }

#pragma unroll
    for (int i = 0; i < 32; ++i)
#pragma unroll
        for (int j = 0; j < 4; ++j) d[i][j] *= 0.125f;
    float mg = -1e30f, mh = -1e30f;
#pragma unroll
    for (int i = 0; i < 32; ++i){
        mg = fmaxf(mg, fmaxf(d[i][0], d[i][1]));
        mh = fmaxf(mh, fmaxf(d[i][2], d[i][3]));
    }
    mg = fmaxf(mg, __shfl_xor_sync(0xffffffffu, mg, 1));
    mg = fmaxf(mg, __shfl_xor_sync(0xffffffffu, mg, 2));
    mh = fmaxf(mh, __shfl_xor_sync(0xffffffffu, mh, 1));
    mh = fmaxf(mh, __shfl_xor_sync(0xffffffffu, mh, 2));
    float sg = 0.f, sh = 0.f;
#pragma unroll
    for (int i = 0; i < 32; ++i){
        d[i][0] = __expf(d[i][0] - mg); d[i][1] = __expf(d[i][1] - mg);
        d[i][2] = __expf(d[i][2] - mh); d[i][3] = __expf(d[i][3] - mh);
        sg += d[i][0] + d[i][1];
        sh += d[i][2] + d[i][3];
    }
    sg += __shfl_xor_sync(0xffffffffu, sg, 1);
    sg += __shfl_xor_sync(0xffffffffu, sg, 2);
    sh += __shfl_xor_sync(0xffffffffu, sh, 1);
    sh += __shfl_xor_sync(0xffffffffu, sh, 2);
    const float ivg = 1.f/sg, ivh = 1.f/sh;

    float d2[8][4];
#pragma unroll
    for (int i = 0; i < 8; ++i)
#pragma unroll
        for (int j = 0; j < 4; ++j) d2[i][j] = 0.f;

#pragma unroll
    for (int kg = 0; kg < 16; ++kg){
        uint32_t a[4];
        a[0] = packh(__float2half_rn(d[kg*2][0]*ivg),   __float2half_rn(d[kg*2][1]*ivg));
        a[1] = packh(__float2half_rn(d[kg*2][2]*ivh),   __float2half_rn(d[kg*2][3]*ivh));
        a[2] = packh(__float2half_rn(d[kg*2+1][0]*ivg), __float2half_rn(d[kg*2+1][1]*ivg));
        a[3] = packh(__float2half_rn(d[kg*2+1][2]*ivh), __float2half_rn(d[kg*2+1][3]*ivh));
#pragma unroll
        for (int np = 0; np < 4; ++np){
            uint32_t bv[4];
            ldsm4(bv, sb + 55296 + (np*16 + r8 + t2*8)*528 + (kg*16 + t1*8)*2);
            mmaf16(d2[np*2],   a, bv[0], bv[1]);
            mmaf16(d2[np*2+1], a, bv[2], bv[3]);
        }
    }

    const int g = lane >> 2, tig = lane & 3;
#pragma unroll
    for (int ni = 0; ni < 8; ++ni){
        const int dc = (ni >> 1)*16 + (ni & 1)*8 + tig*2;
#pragma unroll
        for (int hr = 0; hr < 2; ++hr){
            const int m = m0 + wid*16 + g + hr*8;
            const size_t oi = (size_t)(b*NP + m)*DD + h*64 + dc;
            *(uint32_t*)(oo + oi) = packh(__float2half_rn(d2[ni][hr*2+0]),
                                          __float2half_rn(d2[ni][hr*2+1]));
        }
    }
}

// ---------------- merged prolog: 8 weight transposes + patchify + time-embed ----
__device__ __forceinline__ void tr_tile(const float* __restrict__ in, fp16* __restrict__ out,
                                        int K, int N, int bx, int by, int bz,
                                        float (*tile)[33]){
    const size_t zoff = (size_t)bz * K * N;
    const int n0 = bx*32, k0 = by*32;
    const int lx = threadIdx.x & 31, ly = threadIdx.x >> 5;
#pragma unroll
    for (int rr = 0; rr < 32; rr += 8)
        tile[ly+rr][lx] = in[zoff + (size_t)(k0+ly+rr)*N + n0+lx];
    __syncthreads();
#pragma unroll
    for (int rr = 0; rr < 32; rr += 8)
        out[zoff + (size_t)(n0+ly+rr)*K + k0+lx] = __float2half_rn(tile[lx][ly+rr]);
}

#define PROLOG_BLOCKS 138400
__global__ void __launch_bounds__(256) prolog_k(
    const float* __restrict__ x, const float* __restrict__ cw, const float* __restrict__ cb,
    float* __restrict__ tok, const float* __restrict__ tt, fp16* __restrict__ c0,
    const float* __restrict__ qkvw, fp16* __restrict__ qkvwT,
    const float* __restrict__ ow,   fp16* __restrict__ owT,
    const float* __restrict__ aw,   fp16* __restrict__ awT,
    const float* __restrict__ m1w,  fp16* __restrict__ m1wT,
    const float* __restrict__ m2w,  fp16* __restrict__ m2wT,
    const float* __restrict__ tw1,  fp16* __restrict__ tw1T,
    const float* __restrict__ tw2,  fp16* __restrict__ tw2T,
    const float* __restrict__ faw,  fp16* __restrict__ fawT)
{
    __shared__ float tile[32][33];
    __shared__ float xv[16];
    int b = blockIdx.x;
    if (b < 20736){ int z=b/1728, r=b%1728; tr_tile(qkvw, qkvwT, DD, 3*DD, r%72,  r/72,  z, tile); return; }
    b -= 20736;
    if (b < 6912){  int z=b/576,  r=b%576;  tr_tile(ow,   owT,   DD, DD,   r%24,  r/24,  z, tile); return; }
    b -= 6912;
    if (b < 41472){ int z=b/3456, r=b%3456; tr_tile(aw,   awT,   DD, 6*DD, r%144, r/144, z, tile); return; }
    b -= 41472;
    if (b < 27648){ int z=b/2304, r=b%2304; tr_tile(m1w,  m1wT,  DD, HID,  r%96,  r/96,  z, tile); return; }
    b -= 27648;
    if (b < 27648){ int z=b/2304, r=b%2304; tr_tile(m2w,  m2wT,  HID, DD,  r%24,  r/24,  z, tile); return; }
    b -= 27648;
    if (b < 2304){ tr_tile(tw1, tw1T, DD, HID,  b%96, b/96, 0, tile); return; }
    b -= 2304;
    if (b < 2304){ tr_tile(tw2, tw2T, HID, DD,  b%24, b/24, 0, tile); return; }
    b -= 2304;
    if (b < 1152){ tr_tile(faw, fawT, DD, 2*DD, b%48, b/48, 0, tile); return; }
    b -= 1152;
    if (b < 8192){
        const int t = b, tid = threadIdx.x;
        const int bb = t>>8, n = t&255, gy = n>>4, gx = n&15;
        if (tid < 16){
            int c = tid>>2, p1 = (tid>>1)&1, p2 = tid&1;
            xv[tid] = x[((bb*4+c)*32 + gy*2+p1)*32 + gx*2+p2];
        }
        __syncthreads();
        for (int d = tid; d < DD; d += 256){
            const float4* w4 = (const float4*)(cw + d*16);
            float s = cb[d];
#pragma unroll
            for (int q = 0; q < 4; q++){
                float4 w = w4[q];
                s += xv[q*4+0]*w.x + xv[q*4+1]*w.y + xv[q*4+2]*w.z + xv[q*4+3]*w.w;
            }
            int i2 = d & ~1;
            float ang = (float)n * expf(-(float)i2 * (9.210340371976184f / 768.f));
            float pe = (d & 1) ? cosf(ang) : sinf(ang);
            tok[(size_t)t*DD + d] = s + pe;
        }
        return;
    }
    b -= 8192;
    {   // time embed: b in [0,32)
        for (int j = threadIdx.x; j < 384; j += 256){
            float e = tt[b] * expf(-(float)j * (9.210340371976184f / 383.f));
            c0[b*DD + j]       = __float2half_rn(sinf(e));
            c0[b*DD + 384 + j] = __float2half_rn(cosf(e));
        }
    }
}

// ---------------- layernorm + adaLN modulation (192 threads, float4) --------
__global__ void __launch_bounds__(192) ln_mod_k(
    const float* __restrict__ in, const float* __restrict__ ada,
    int adaStride, int shOff, int scOff, fp16* __restrict__ out){
    const int t = blockIdx.x, tid = threadIdx.x;   // 192 threads x float4 = 768
    const float4 xx = *(const float4*)(in + (size_t)t*DD + tid*4);
    float sum = xx.x + xx.y + xx.z + xx.w;
    float sq  = fmaf(xx.x,xx.x, fmaf(xx.y,xx.y, fmaf(xx.z,xx.z, xx.w*xx.w)));
    __shared__ float s1[6], s2[6];
#pragma unroll
    for (int o = 16; o; o >>= 1){
        sum += __shfl_xor_sync(0xffffffffu, sum, o);
        sq  += __shfl_xor_sync(0xffffffffu, sq,  o);
    }
    if ((tid & 31) == 0){ s1[tid>>5] = sum; s2[tid>>5] = sq; }
    __syncthreads();
    float tot = 0.f, totq = 0.f;
#pragma unroll
    for (int w = 0; w < 6; w++){ tot += s1[w]; totq += s2[w]; }
    const float m   = tot * (1.f/768.f);
    const float var = totq * (1.f/768.f) - m*m;
    const float rr  = rsqrtf(var + 1e-6f);
    const int b = t >> 8;
    const float4 shv = *(const float4*)(ada + (size_t)b*adaStride + shOff + tid*4);
    const float4 scv = *(const float4*)(ada + (size_t)b*adaStride + scOff + tid*4);
    const float y0 = (xx.x-m)*rr*(1.f+scv.x) + shv.x;
    const float y1 = (xx.y-m)*rr*(1.f+scv.y) + shv.y;
    const float y2 = (xx.z-m)*rr*(1.f+scv.z) + shv.z;
    const float y3 = (xx.w-m)*rr*(1.f+scv.w) + shv.w;
    uint2 ov;
    ov.x = packh(__float2half_rn(y0), __float2half_rn(y1));
    ov.y = packh(__float2half_rn(y2), __float2half_rn(y3));
    *(uint2*)(out + (size_t)t*DD + tid*4) = ov;
}

// ---------------- final head + unpatchify ----------------
__global__ void final_k(const fp16* __restrict__ hmod, const float* __restrict__ w,
                        const float* __restrict__ bias, float* __restrict__ out){
    __shared__ float row[768];
    __shared__ float red[128];
    const int t = blockIdx.x, tid = threadIdx.x;  // 128 threads
#pragma unroll
    for (int rr = 0; rr < 6; rr++)
        row[tid + rr*128] = __half2float(hmod[(size_t)t*DD + tid + rr*128]);
    __syncthreads();
    const int j = tid & 15, p = tid >> 4;
    float s = 0.f;
#pragma unroll 8
    for (int k = p*96; k < p*96 + 96; ++k) s = fmaf(row[k], w[k*16 + j], s);
    red[tid] = s;
    __syncthreads();
    if (tid < 16){
        float tot = bias[tid];
#pragma unroll
        for (int q = 0; q < 8; q++) tot += red[q*16 + tid];
        const int b = t>>8, n = t&255, gy = n>>4, gx = n&15;
        const int c = tid&3, pq = tid>>2, p1 = pq>>1, p2 = pq&1;
        out[((b*4+c)*32 + gy*2+p1)*32 + gx*2+p2] = tot;
    }
}

// ---------------- host launcher ----------------
extern "C" void kernel_launch(void* const* d_in, const int* in_sizes, int n_in,
                              void* d_out, int out_size){
    (void)in_sizes; (void)n_in; (void)out_size;
    const float* x     = (const float*)d_in[0];
    const float* tt    = (const float*)d_in[1];
    const float* convw = (const float*)d_in[2];
    const float* convb = (const float*)d_in[3];
    const float* tw1   = (const float*)d_in[4];
    const float* tb1   = (const float*)d_in[5];
    const float* tw2   = (const float*)d_in[6];
    const float* tb2   = (const float*)d_in[7];
    const float* cls   = (const float*)d_in[8];
    const float* qkvw  = (const float*)d_in[9];
    const float* qkvb  = (const float*)d_in[10];
    const float* ow    = (const float*)d_in[11];
    const float* ob    = (const float*)d_in[12];
    const float* aw    = (const float*)d_in[13];
    const float* ab    = (const float*)d_in[14];
    const float* m1w   = (const float*)d_in[15];
    const float* m1b   = (const float*)d_in[16];
    const float* m2w   = (const float*)d_in[17];
    const float* m2b   = (const float*)d_in[18];
    const float* faw   = (const float*)d_in[19];
    const float* fab   = (const float*)d_in[20];
    const float* flw   = (const float*)d_in[21];
    const float* flb   = (const float*)d_in[22];
    const int*   lab   = (const int*)d_in[23];
    float* out = (float*)d_out;

    float *tok,*ada,*adaf;
    fp16 *hmod,*qkv,*oo,*hmid,*c0,*tmid,*sc;
    fp16 *qkvwT,*owT,*m1wT,*m2wT,*awT,*tw1T,*tw2T,*fawT;
    cudaGetSymbolAddress((void**)&tok,  g_tok);
    cudaGetSymbolAddress((void**)&ada,  g_ada);
    cudaGetSymbolAddress((void**)&adaf, g_adaf);
    cudaGetSymbolAddress((void**)&hmod, g_hmod);
    cudaGetSymbolAddress((void**)&qkv,  g_qkv);
    cudaGetSymbolAddress((void**)&oo,   g_oo);
    cudaGetSymbolAddress((void**)&hmid, g_hmid);
    cudaGetSymbolAddress((void**)&c0,   g_c0);
    cudaGetSymbolAddress((void**)&tmid, g_tmid);
    cudaGetSymbolAddress((void**)&sc,   g_sc);
    cudaGetSymbolAddress((void**)&qkvwT,g_qkvwT);
    cudaGetSymbolAddress((void**)&owT,  g_owT);
    cudaGetSymbolAddress((void**)&m1wT, g_m1wT);
    cudaGetSymbolAddress((void**)&m2wT, g_m2wT);
    cudaGetSymbolAddress((void**)&awT,  g_awT);
    cudaGetSymbolAddress((void**)&tw1T, g_tw1T);
    cudaGetSymbolAddress((void**)&tw2T, g_tw2T);
    cudaGetSymbolAddress((void**)&fawT, g_fawT);

    cudaFuncSetAttribute((void*)gemm_fp16<0,32,128>,  cudaFuncAttributeMaxDynamicSharedMemorySize, GSM32);
    cudaFuncSetAttribute((void*)gemm_fp16<3,32,128>,  cudaFuncAttributeMaxDynamicSharedMemorySize, GSM32);
    cudaFuncSetAttribute((void*)gemm_fp16<6,32,128>,  cudaFuncAttributeMaxDynamicSharedMemorySize, GSM32);
    cudaFuncSetAttribute((void*)gemm_fp16<1,128,128>, cudaFuncAttributeMaxDynamicSharedMemorySize, GSM128);
    cudaFuncSetAttribute((void*)gemm_fp16<5,128,128>, cudaFuncAttributeMaxDynamicSharedMemorySize, GSM128);
    cudaFuncSetAttribute((void*)gemm_fp16<2,128,64>,  cudaFuncAttributeMaxDynamicSharedMemorySize, GSM64);
    cudaFuncSetAttribute((void*)fused_attn, cudaFuncAttributeMaxDynamicSharedMemorySize, FA_SMEM);

    // #1: merged prolog (all transposes + patchify + time-embed)
    prolog_k<<<PROLOG_BLOCKS, 256>>>(x, convw, convb, tok, tt, c0,
        qkvw, qkvwT, ow, owT, aw, awT, m1w, m1wT, m2w, m2wT,
        tw1, tw1T, tw2, tw2T, faw, fawT);

    // conditioning on M=32 tiles (silu fused into tmlp2 epilogue)
    gemm_fp16<3,32,128><<<dim3(HID/128, 1, 1), 256, GSM32>>>(c0, DD, tw1T, tb1,
        nullptr, tmid, 32, HID, DD, nullptr, 0, nullptr, 0, 0, 0);
    gemm_fp16<6,32,128><<<dim3(DD/128, 1, 1), 256, GSM32>>>(tmid, HID, tw2T, tb2,
        nullptr, sc, 32, DD, HID, cls, 0, lab, 0, 0, 0);
    gemm_fp16<0,32,128><<<dim3(6*DD/128, 1, LL), 256, GSM32>>>(sc, DD, awT, ab,
        ada, nullptr, 32, 6*DD, DD, nullptr, 0, nullptr,
        (long long)6*DD*DD, (long long)6*DD, (long long)BB*6*DD);

    ln_mod_k<<<TT, 192>>>(tok, ada, 6*DD, 0, DD, hmod);
    for (int i = 0; i < LL; i++){
        const float* adaL = ada + (size_t)i*BB*6*DD;
        gemm_fp16<5,128,128><<<dim3(3*DD/128, TT/128, 1), 256, GSM128>>>(hmod, DD,
            qkvwT + (size_t)i*3*DD*DD, qkvb + (size_t)i*3*DD,
            nullptr, qkv, TT, 3*DD, DD, nullptr, 0, nullptr, 0, 0, 0);
        fused_attn<<<dim3(2, BHH), 256, FA_SMEM>>>(qkv, oo);
        gemm_fp16<2,128,64><<<dim3(DD/64, TT/128, 1), 256, GSM64>>>(oo, DD,
            owT + (size_t)i*DD*DD, ob + (size_t)i*DD,
            tok, nullptr, TT, DD, DD, adaL, 2*DD, nullptr, 0, 0, 0);
        // mlp branch
        ln_mod_k<<<TT, 192>>>(tok, adaL, 6*DD, 3*DD, 4*DD, hmod);
        gemm_fp16<1,128,128><<<dim3(HID/128, TT/128, 1), 256, GSM128>>>(hmod, DD,
            m1wT + (size_t)i*HID*DD, m1b + (size_t)i*HID,
            nullptr, hmid, TT, HID, DD, nullptr, 0, nullptr, 0, 0, 0);
        gemm_fp16<2,128,64><<<dim3(DD/64, TT/128, 1), 256, GSM64>>>(hmid, HID,
            m2wT + (size_t)i*DD*HID, m2b + (size_t)i*DD,
            tok, nullptr, TT, DD, HID, adaL, 5*DD, nullptr, 0, 0, 0);
        if (i + 1 < LL)
            ln_mod_k<<<TT, 192>>>(tok, ada + (size_t)(i+1)*BB*6*DD, 6*DD, 0, DD, hmod);
    }

    gemm_fp16<0,32,128><<<dim3(2*DD/128, 1, 1), 256, GSM32>>>(sc, DD, fawT, fab,
        adaf, nullptr, 32, 2*DD, DD, nullptr, 0, nullptr, 0, 0, 0);
    ln_mod_k<<<TT, 192>>>(tok, adaf, 2*DD, 0, DD, hmod);
    final_k<<<TT, 128>>>(hmod, flw, flb, out);
}

// round 16
// speedup vs baseline: 1.0509x; 1.0509x over previous
#include <cuda_runtime.h>
#include <cuda_fp16.h>
#include <math.h>
#include <stdint.h>

#define BB   32
#define DD   768
#define LL   12
#define HID  3072
#define NP   256
#define TT   8192
#define BHH  384

typedef __half fp16;

// ---------------- scratch (static device allocations) ----------------
__device__ float g_tok [TT*DD];
__device__ float g_ada [LL*BB*6*DD];
__device__ float g_adaf[BB*2*DD];
// fp16 activations
__device__ fp16 g_hmod[TT*DD];
__device__ fp16 g_qkv[(size_t)TT*3*DD];
__device__ fp16 g_oo[TT*DD];
__device__ fp16 g_hmid[(size_t)TT*HID];
__device__ fp16 g_c0 [32*DD];
__device__ fp16 g_tmid[(size_t)32*HID];
__device__ fp16 g_sc [32*DD];
// transposed fp16 weights [N][K]
__device__ fp16 g_qkvwT[(size_t)LL*3*DD*DD];
__device__ fp16 g_owT [(size_t)LL*DD*DD];
__device__ fp16 g_m1wT[(size_t)LL*HID*DD];
__device__ fp16 g_m2wT[(size_t)LL*DD*HID];
__device__ fp16 g_awT [(size_t)LL*6*DD*DD];
__device__ fp16 g_tw1T[(size_t)HID*DD];
__device__ fp16 g_tw2T[(size_t)DD*HID];
__device__ fp16 g_fawT[(size_t)2*DD*DD];

// ---------------- helpers ----------------
__device__ __forceinline__ uint32_t sm32(const void* p){
    uint32_t a;
    asm("{ .reg .u64 t; cvta.to.shared.u64 t, %1; cvt.u32.u64 %0, t; }" : "=r"(a) : "l"(p));
    return a;
}
__device__ __forceinline__ void cp16(uint32_t dst, const void* src){
    asm volatile("cp.async.cg.shared.global [%0], [%1], 16;" :: "r"(dst), "l"(src) : "memory");
}
__device__ __forceinline__ void ldsm4(uint32_t* r, uint32_t addr){
    asm volatile("ldmatrix.sync.aligned.m8n8.x4.shared.b16 {%0,%1,%2,%3}, [%4];"
        : "=r"(r[0]), "=r"(r[1]), "=r"(r[2]), "=r"(r[3]) : "r"(addr));
}
__device__ __forceinline__ void mmaf16(float* d, const uint32_t* a, uint32_t b0, uint32_t b1){
    asm volatile("mma.sync.aligned.m16n8k16.row.col.f32.f16.f16.f32 "
        "{%0,%1,%2,%3}, {%4,%5,%6,%7}, {%8,%9}, {%0,%1,%2,%3};"
        : "+f"(d[0]), "+f"(d[1]), "+f"(d[2]), "+f"(d[3])
        : "r"(a[0]), "r"(a[1]), "r"(a[2]), "r"(a[3]), "r"(b0), "r"(b1));
}
__device__ __forceinline__ uint32_t packh(fp16 a, fp16 b){
    return (uint32_t)__half_as_ushort(a) | ((uint32_t)__half_as_ushort(b) << 16);
}
__device__ __forceinline__ float gelu_f(float x){
    return 0.5f * x * (1.0f + erff(x * 0.7071067811865475f));
}
__device__ __forceinline__ float silu_f(float x){
    return x / (1.f + expf(-x));
}

// ---- fp16 K=64 chunk, row stride 144B
template<int MI>
__device__ __forceinline__ void mma64_chunk(uint32_t sb, int oA, int oB,
                                            int mrow0, int ncol0, int lane, float (*d)[4]){
    const int r8 = lane & 7, t1 = (lane >> 3) & 1, t2 = (lane >> 4) & 1;
#pragma unroll
    for (int ks = 0; ks < 4; ++ks){
        uint32_t a[MI][4], b[2][4];
        const int keA = ks*16 + t2*8;
        const int keB = ks*16 + t1*8;
#pragma unroll
        for (int mi = 0; mi < MI; ++mi)
            ldsm4(a[mi], sb + oA + (mrow0 + mi*16 + r8 + t1*8)*144 + keA*2);
#pragma unroll
        for (int p = 0; p < 2; ++p)
            ldsm4(b[p], sb + oB + (ncol0 + p*16 + r8 + t2*8)*144 + keB*2);
#pragma unroll
        for (int mi = 0; mi < MI; ++mi)
#pragma unroll
            for (int p = 0; p < 2; ++p){
                mmaf16(d[mi*4+p*2],   a[mi], b[p][0], b[p][1]);
                mmaf16(d[mi*4+p*2+1], a[mi], b[p][2], b[p][3]);
            }
    }
}

// ---------------- main GEMM: out[M,N] = A[M,K] @ W[N,K]^T ----------
// MTx128 CTA tile (MT=128 or 32), 8 warps, K=64 chunks, 3-stage ring, depth-2.
// EPI: 0 fp32 | 1 gelu fp16 | 2 gated residual fp32 | 3 silu fp16 | 4 +cls fp32 |
//      5 fp16 | 6 (+cls then silu) fp16
template<int EPI, int MT>
__global__ void __launch_bounds__(256, 2) gemm_fp16(
    const fp16* __restrict__ A, int lda,
    const fp16* __restrict__ W,
    const float* __restrict__ bias,
    float* __restrict__ outF, fp16* __restrict__ outH,
    int Mvalid, int N, int K,
    const float* __restrict__ aux, int auxOff, const int* __restrict__ lab,
    long long wz, long long bz, long long oz)
{
    constexpr int MI   = MT / 32;           // 4 or 1
    constexpr int ASTG = MT * 144;
    constexpr int STGB = ASTG + 128 * 144;
    extern __shared__ char smem[];
    const uint32_t sb = sm32(smem);
    const int tid = threadIdx.x, lane = tid & 31, wid = tid >> 5;
    const int warpM = wid & 1, warpN = wid >> 1;
    const int m0 = blockIdx.y*MT, n0 = blockIdx.x*128, z = blockIdx.z;
    const fp16* WZ = W + (size_t)z*wz;
    const float* BzP = bias + (size_t)z*bz;

    float d[MI*4][4];
#pragma unroll
    for (int i = 0; i < MI*4; ++i)
#pragma unroll
        for (int j = 0; j < 4; ++j) d[i][j] = 0.f;

    auto issue = [&](int s, int t){
        const int kt = t << 6;
        const uint32_t base = sb + s*STGB;
#pragma unroll
        for (int it = 0; it < MT/32; ++it){
            const int idx = tid + it*256;
            const int row = idx >> 3, q = idx & 7;
            cp16(base + row*144 + q*16, A + (size_t)(m0+row)*lda + kt + q*8);
        }
#pragma unroll
        for (int it = 0; it < 4; ++it){
            const int idx = tid + it*256;
            const int row = idx >> 3, q = idx & 7;
            cp16(base + ASTG + row*144 + q*16, WZ + (size_t)(n0+row)*K + kt + q*8);
        }
        asm volatile("cp.async.commit_group;" ::: "memory");
    };

    const int nk = K >> 6;
    issue(0, 0); issue(1, 1);
    for (int t = 0; t < nk; ++t){
        asm volatile("cp.async.wait_group 1;" ::: "memory");
        __syncthreads();
        if (t + 2 < nk) issue((t + 2) % 3, t + 2);
        else asm volatile("cp.async.commit_group;" ::: "memory");
        const int s = t % 3;
        mma64_chunk<MI>(sb + s*STGB, 0, ASTG, warpM*(MI*16), warpN*32, lane, d);
    }

    const int g = lane >> 2, tig = lane & 3;
#pragma unroll
    for (int mi = 0; mi < MI; ++mi){
#pragma unroll
        for (int ni = 0; ni < 4; ++ni){
            const int n = n0 + warpN*32 + ni*8 + tig*2;
            const float2 bv = *(const float2*)(BzP + n);
#pragma unroll
            for (int hr = 0; hr < 2; ++hr){
                const int m = m0 + warpM*(MI*16) + mi*16 + g + hr*8;
                if (m < Mvalid){
                    float x0 = d[mi*4+ni][hr*2+0] + bv.x;
                    float x1 = d[mi*4+ni][hr*2+1] + bv.y;
                    const size_t oi = (size_t)m*N + n;
                    if (EPI == 0){
                        *(float2*)(outF + (size_t)z*oz + oi) = make_float2(x0, x1);
                    } else if (EPI == 2){
                        const float2 gv = *(const float2*)(aux + (size_t)(m>>8)*(6*DD) + auxOff + n);
                        float2 ov = *(float2*)(outF + oi);
                        *(float2*)(outF + oi) = make_float2(ov.x + gv.x*x0, ov.y + gv.y*x1);
                    } else if (EPI == 4){
                        const float2 cv = *(const float2*)(aux + (size_t)lab[m]*DD + n);
                        *(float2*)(outF + oi) = make_float2(x0 + cv.x, x1 + cv.y);
                    } else if (EPI == 6){
                        const float2 cv = *(const float2*)(aux + (size_t)lab[m]*DD + n);
                        x0 = silu_f(x0 + cv.x); x1 = silu_f(x1 + cv.y);
                        *(uint32_t*)(outH + oi) = packh(__float2half_rn(x0), __float2half_rn(x1));
                    } else {
                        if (EPI == 1){ x0 = gelu_f(x0); x1 = gelu_f(x1); }
                        else if (EPI == 3){ x0 = silu_f(x0); x1 = silu_f(x1); }
                        *(uint32_t*)(outH + oi) = packh(__float2half_rn(x0), __float2half_rn(x1));
                    }
                }
            }
        }
    }
}
#define GSM128 (3*(128*144 + 128*144))
#define GSM32  (3*(32*144  + 128*144))

// ---------------- fused flash attention: O = softmax(QK^T/8) @ V ----------
// CTA: 128 query rows x all 256 keys; warp tile = 16 rows x 256 cols.
// smem: Q@0 (128x144), K@18432 (256x144), VT@55296 (64 rows x 528B). total 89088.
// Q/K staged via cp.async, overlapped with the register-path V transpose.
#define FA_SMEM 89088
__global__ void __launch_bounds__(256) fused_attn(const fp16* __restrict__ qkv,
                                                  fp16* __restrict__ oo){
    extern __shared__ char smem[];
    const uint32_t sb = sm32(smem);
    const int tid = threadIdx.x, lane = tid & 31, wid = tid >> 5;
    const int z = blockIdx.y, b = z/12, h = z%12;
    const int m0 = blockIdx.x*128;
    const size_t qbase = (size_t)b*NP*2304 + h*64;
    const size_t vbase = qbase + 1536;

    {
        // async Q (128 rows x 128B) and K (256 rows x 128B)
        const int lrow = tid >> 1, lq = tid & 1;
        const size_t qr = qbase + (size_t)(m0+lrow)*2304 + lq*32;
#pragma unroll
        for (int j = 0; j < 4; ++j)
            cp16(sb + lrow*144 + lq*64 + j*16, qkv + qr + j*8);
        const size_t kr = qbase + 768 + (size_t)tid*2304;
#pragma unroll
        for (int j = 0; j < 8; ++j)
            cp16(sb + 18432 + tid*144 + j*16, qkv + kr + j*8);
        asm volatile("cp.async.commit_group;" ::: "memory");

        // V transpose via registers (overlaps with async Q/K)
        const int vk = tid >> 3, vn8 = tid & 7;
#pragma unroll
        for (int it = 0; it < 8; ++it){
            const int k = it*32 + vk;
            const uint32_t* vv = (const uint32_t*)(qkv + vbase + (size_t)k*2304 + vn8*8);
#pragma unroll
            for (int w = 0; w < 4; ++w){
                const uint32_t pr = vv[w];
                const int dc = vn8*8 + w*2;
                *(fp16*)(smem + 55296 + dc*528 + k*2)     = __ushort_as_half((unsigned short)(pr & 0xffff));
                *(fp16*)(smem + 55296 + (dc+1)*528 + k*2) = __ushort_as_half((unsigned short)(pr >> 16));
            }
        }
        asm volatile("cp.async.wait_group 0;" ::: "memory");
    }
    __syncthreads();

    const int r8 = lane & 7, t1 = (lane >> 3) & 1, t2 = (lane >> 4) & 1;

    float d[32][4];
#pragma unroll
    for (int i = 0; i < 32; ++i)
#pragma unroll
        for (int j = 0; j < 4; ++j) d[i][j] = 0.f;

    const uint32_t qoff = sb + (wid*16 + r8 + t1*8)*144;
#pragma unroll
    for (int kc = 0; kc < 4; ++kc){
        uint32_t a[4];
        ldsm4(a, qoff + (kc*16 + t2*8)*2);
#pragma unroll
        for (int p = 0; p < 16; ++p){
            uint32_t bq[4];
            ldsm4(bq, sb + 18432 + (p*16 + r8 + t2*8)*144 + (kc*16 + t1*8)*2);
            mmaf16(d[p*2],   a, bq[0], bq[1]);
            mmaf16(d[p*2+1], a, bq[2], bq[3]);
        }
    }

#pragma unroll
    for (int i = 0; i < 32; ++i)
#pragma unroll
        for (int j = 0; j < 4; ++j) d[i][j] *= 0.125f;
    float mg = -1e30f, mh = -1e30f;
#pragma unroll
    for (int i = 0; i < 32; ++i){
        mg = fmaxf(mg, fmaxf(d[i][0], d[i][1]));
        mh = fmaxf(mh, fmaxf(d[i][2], d[i][3]));
    }
    mg = fmaxf(mg, __shfl_xor_sync(0xffffffffu, mg, 1));
    mg = fmaxf(mg, __shfl_xor_sync(0xffffffffu, mg, 2));
    mh = fmaxf(mh, __shfl_xor_sync(0xffffffffu, mh, 1));
    mh = fmaxf(mh, __shfl_xor_sync(0xffffffffu, mh, 2));
    float sg = 0.f, sh = 0.f;
#pragma unroll
    for (int i = 0; i < 32; ++i){
        d[i][0] = __expf(d[i][0] - mg); d[i][1] = __expf(d[i][1] - mg);
        d[i][2] = __expf(d[i][2] - mh); d[i][3] = __expf(d[i][3] - mh);
        sg += d[i][0] + d[i][1];
        sh += d[i][2] + d[i][3];
    }
    sg += __shfl_xor_sync(0xffffffffu, sg, 1);
    sg += __shfl_xor_sync(0xffffffffu, sg, 2);
    sh += __shfl_xor_sync(0xffffffffu, sh, 1);
    sh += __shfl_xor_sync(0xffffffffu, sh, 2);
    const float ivg = 1.f/sg, ivh = 1.f/sh;

    float d2[8][4];
#pragma unroll
    for (int i = 0; i < 8; ++i)
#pragma unroll
        for (int j = 0; j < 4; ++j) d2[i][j] = 0.f;

#pragma unroll
    for (int kg = 0; kg < 16; ++kg){
        uint32_t a[4];
        a[0] = packh(__float2half_rn(d[kg*2][0]*ivg),   __float2half_rn(d[kg*2][1]*ivg));
        a[1] = packh(__float2half_rn(d[kg*2][2]*ivh),   __float2half_rn(d[kg*2][3]*ivh));
        a[2] = packh(__float2half_rn(d[kg*2+1][0]*ivg), __float2half_rn(d[kg*2+1][1]*ivg));
        a[3] = packh(__float2half_rn(d[kg*2+1][2]*ivh), __float2half_rn(d[kg*2+1][3]*ivh));
#pragma unroll
        for (int np = 0; np < 4; ++np){
            uint32_t bv[4];
            ldsm4(bv, sb + 55296 + (np*16 + r8 + t2*8)*528 + (kg*16 + t1*8)*2);
            mmaf16(d2[np*2],   a, bv[0], bv[1]);
            mmaf16(d2[np*2+1], a, bv[2], bv[3]);
        }
    }

    const int g = lane >> 2, tig = lane & 3;
#pragma unroll
    for (int ni = 0; ni < 8; ++ni){
        const int dc = (ni >> 1)*16 + (ni & 1)*8 + tig*2;
#pragma unroll
        for (int hr = 0; hr < 2; ++hr){
            const int m = m0 + wid*16 + g + hr*8;
            const size_t oi = (size_t)(b*NP + m)*DD + h*64 + dc;
            *(uint32_t*)(oo + oi) = packh(__float2half_rn(d2[ni][hr*2+0]),
                                          __float2half_rn(d2[ni][hr*2+1]));
        }
    }
}

// ---------------- merged prolog: 8 weight transposes + patchify + time-embed ----
__device__ __forceinline__ void tr_tile(const float* __restrict__ in, fp16* __restrict__ out,
                                        int K, int N, int bx, int by, int bz,
                                        float (*tile)[33]){
    const size_t zoff = (size_t)bz * K * N;
    const int n0 = bx*32, k0 = by*32;
    const int lx = threadIdx.x & 31, ly = threadIdx.x >> 5;
#pragma unroll
    for (int rr = 0; rr < 32; rr += 8)
        tile[ly+rr][lx] = in[zoff + (size_t)(k0+ly+rr)*N + n0+lx];
    __syncthreads();
#pragma unroll
    for (int rr = 0; rr < 32; rr += 8)
        out[zoff + (size_t)(n0+ly+rr)*K + k0+lx] = __float2half_rn(tile[lx][ly+rr]);
}

#define PROLOG_BLOCKS 138400
__global__ void __launch_bounds__(256) prolog_k(
    const float* __restrict__ x, const float* __restrict__ cw, const float* __restrict__ cb,
    float* __restrict__ tok, const float* __restrict__ tt, fp16* __restrict__ c0,
    const float* __restrict__ qkvw, fp16* __restrict__ qkvwT,
    const float* __restrict__ ow,   fp16* __restrict__ owT,
    const float* __restrict__ aw,   fp16* __restrict__ awT,
    const float* __restrict__ m1w,  fp16* __restrict__ m1wT,
    const float* __restrict__ m2w,  fp16* __restrict__ m2wT,
    const float* __restrict__ tw1,  fp16* __restrict__ tw1T,
    const float* __restrict__ tw2,  fp16* __restrict__ tw2T,
    const float* __restrict__ faw,  fp16* __restrict__ fawT)
{
    __shared__ float tile[32][33];
    __shared__ float xv[16];
    int b = blockIdx.x;
    if (b < 20736){ int z=b/1728, r=b%1728; tr_tile(qkvw, qkvwT, DD, 3*DD, r%72,  r/72,  z, tile); return; }
    b -= 20736;
    if (b < 6912){  int z=b/576,  r=b%576;  tr_tile(ow,   owT,   DD, DD,   r%24,  r/24,  z, tile); return; }
    b -= 6912;
    if (b < 41472){ int z=b/3456, r=b%3456; tr_tile(aw,   awT,   DD, 6*DD, r%144, r/144, z, tile); return; }
    b -= 41472;
    if (b < 27648){ int z=b/2304, r=b%2304; tr_tile(m1w,  m1wT,  DD, HID,  r%96,  r/96,  z, tile); return; }
    b -= 27648;
    if (b < 27648){ int z=b/2304, r=b%2304; tr_tile(m2w,  m2wT,  HID, DD,  r%24,  r/24,  z, tile); return; }
    b -= 27648;
    if (b < 2304){ tr_tile(tw1, tw1T, DD, HID,  b%96, b/96, 0, tile); return; }
    b -= 2304;
    if (b < 2304){ tr_tile(tw2, tw2T, HID, DD,  b%24, b/24, 0, tile); return; }
    b -= 2304;
    if (b < 1152){ tr_tile(faw, fawT, DD, 2*DD, b%48, b/48, 0, tile); return; }
    b -= 1152;
    if (b < 8192){
        const int t = b, tid = threadIdx.x;
        const int bb = t>>8, n = t&255, gy = n>>4, gx = n&15;
        if (tid < 16){
            int c = tid>>2, p1 = (tid>>1)&1, p2 = tid&1;
            xv[tid] = x[((bb*4+c)*32 + gy*2+p1)*32 + gx*2+p2];
        }
        __syncthreads();
        for (int d = tid; d < DD; d += 256){
            const float4* w4 = (const float4*)(cw + d*16);
            float s = cb[d];
#pragma unroll
            for (int q = 0; q < 4; q++){
                float4 w = w4[q];
                s += xv[q*4+0]*w.x + xv[q*4+1]*w.y + xv[q*4+2]*w.z + xv[q*4+3]*w.w;
            }
            int i2 = d & ~1;
            float ang = (float)n * expf(-(float)i2 * (9.210340371976184f / 768.f));
            float pe = (d & 1) ? cosf(ang) : sinf(ang);
            tok[(size_t)t*DD + d] = s + pe;
        }
        return;
    }
    b -= 8192;
    {   // time embed: b in [0,32)
        for (int j = threadIdx.x; j < 384; j += 256){
            float e = tt[b] * expf(-(float)j * (9.210340371976184f / 383.f));
            c0[b*DD + j]       = __float2half_rn(sinf(e));
            c0[b*DD + 384 + j] = __float2half_rn(cosf(e));
        }
    }
}

// ---------------- layernorm + adaLN modulation (192 threads, float4) --------
__global__ void __launch_bounds__(192) ln_mod_k(
    const float* __restrict__ in, const float* __restrict__ ada,
    int adaStride, int shOff, int scOff, fp16* __restrict__ out){
    const int t = blockIdx.x, tid = threadIdx.x;   // 192 threads x float4 = 768
    const float4 xx = *(const float4*)(in + (size_t)t*DD + tid*4);
    float sum = xx.x + xx.y + xx.z + xx.w;
    float sq  = fmaf(xx.x,xx.x, fmaf(xx.y,xx.y, fmaf(xx.z,xx.z, xx.w*xx.w)));
    __shared__ float s1[6], s2[6];
#pragma unroll
    for (int o = 16; o; o >>= 1){
        sum += __shfl_xor_sync(0xffffffffu, sum, o);
        sq  += __shfl_xor_sync(0xffffffffu, sq,  o);
    }
    if ((tid & 31) == 0){ s1[tid>>5] = sum; s2[tid>>5] = sq; }
    __syncthreads();
    float tot = 0.f, totq = 0.f;
#pragma unroll
    for (int w = 0; w < 6; w++){ tot += s1[w]; totq += s2[w]; }
    const float m   = tot * (1.f/768.f);
    const float var = totq * (1.f/768.f) - m*m;
    const float rr  = rsqrtf(var + 1e-6f);
    const int b = t >> 8;
    const float4 shv = *(const float4*)(ada + (size_t)b*adaStride + shOff + tid*4);
    const float4 scv = *(const float4*)(ada + (size_t)b*adaStride + scOff + tid*4);
    const float y0 = (xx.x-m)*rr*(1.f+scv.x) + shv.x;
    const float y1 = (xx.y-m)*rr*(1.f+scv.y) + shv.y;
    const float y2 = (xx.z-m)*rr*(1.f+scv.z) + shv.z;
    const float y3 = (xx.w-m)*rr*(1.f+scv.w) + shv.w;
    uint2 ov;
    ov.x = packh(__float2half_rn(y0), __float2half_rn(y1));
    ov.y = packh(__float2half_rn(y2), __float2half_rn(y3));
    *(uint2*)(out + (size_t)t*DD + tid*4) = ov;
}

// ---------------- final head + unpatchify ----------------
__global__ void final_k(const fp16* __restrict__ hmod, const float* __restrict__ w,
                        const float* __restrict__ bias, float* __restrict__ out){
    __shared__ float row[768];
    __shared__ float red[128];
    const int t = blockIdx.x, tid = threadIdx.x;  // 128 threads
#pragma unroll
    for (int rr = 0; rr < 6; rr++)
        row[tid + rr*128] = __half2float(hmod[(size_t)t*DD + tid + rr*128]);
    __syncthreads();
    const int j = tid & 15, p = tid >> 4;
    float s = 0.f;
#pragma unroll 8
    for (int k = p*96; k < p*96 + 96; ++k) s = fmaf(row[k], w[k*16 + j], s);
    red[tid] = s;
    __syncthreads();
    if (tid < 16){
        float tot = bias[tid];
#pragma unroll
        for (int q = 0; q < 8; q++) tot += red[q*16 + tid];
        const int b = t>>8, n = t&255, gy = n>>4, gx = n&15;
        const int c = tid&3, pq = tid>>2, p1 = pq>>1, p2 = pq&1;
        out[((b*4+c)*32 + gy*2+p1)*32 + gx*2+p2] = tot;
    }
}

// ---------------- host launcher ----------------
extern "C" void kernel_launch(void* const* d_in, const int* in_sizes, int n_in,
                              void* d_out, int out_size){
    (void)in_sizes; (void)n_in; (void)out_size;
    const float* x     = (const float*)d_in[0];
    const float* tt    = (const float*)d_in[1];
    const float* convw = (const float*)d_in[2];
    const float* convb = (const float*)d_in[3];
    const float* tw1   = (const float*)d_in[4];
    const float* tb1   = (const float*)d_in[5];
    const float* tw2   = (const float*)d_in[6];
    const float* tb2   = (const float*)d_in[7];
    const float* cls   = (const float*)d_in[8];
    const float* qkvw  = (const float*)d_in[9];
    const float* qkvb  = (const float*)d_in[10];
    const float* ow    = (const float*)d_in[11];
    const float* ob    = (const float*)d_in[12];
    const float* aw    = (const float*)d_in[13];
    const float* ab    = (const float*)d_in[14];
    const float* m1w   = (const float*)d_in[15];
    const float* m1b   = (const float*)d_in[16];
    const float* m2w   = (const float*)d_in[17];
    const float* m2b   = (const float*)d_in[18];
    const float* faw   = (const float*)d_in[19];
    const float* fab   = (const float*)d_in[20];
    const float* flw   = (const float*)d_in[21];
    const float* flb   = (const float*)d_in[22];
    const int*   lab   = (const int*)d_in[23];
    float* out = (float*)d_out;

    float *tok,*ada,*adaf;
    fp16 *hmod,*qkv,*oo,*hmid,*c0,*tmid,*sc;
    fp16 *qkvwT,*owT,*m1wT,*m2wT,*awT,*tw1T,*tw2T,*fawT;
    cudaGetSymbolAddress((void**)&tok,  g_tok);
    cudaGetSymbolAddress((void**)&ada,  g_ada);
    cudaGetSymbolAddress((void**)&adaf, g_adaf);
    cudaGetSymbolAddress((void**)&hmod, g_hmod);
    cudaGetSymbolAddress((void**)&qkv,  g_qkv);
    cudaGetSymbolAddress((void**)&oo,   g_oo);
    cudaGetSymbolAddress((void**)&hmid, g_hmid);
    cudaGetSymbolAddress((void**)&c0,   g_c0);
    cudaGetSymbolAddress((void**)&tmid, g_tmid);
    cudaGetSymbolAddress((void**)&sc,   g_sc);
    cudaGetSymbolAddress((void**)&qkvwT,g_qkvwT);
    cudaGetSymbolAddress((void**)&owT,  g_owT);
    cudaGetSymbolAddress((void**)&m1wT, g_m1wT);
    cudaGetSymbolAddress((void**)&m2wT, g_m2wT);
    cudaGetSymbolAddress((void**)&awT,  g_awT);
    cudaGetSymbolAddress((void**)&tw1T, g_tw1T);
    cudaGetSymbolAddress((void**)&tw2T, g_tw2T);
    cudaGetSymbolAddress((void**)&fawT, g_fawT);

    cudaFuncSetAttribute(gemm_fp16<0,32>,  cudaFuncAttributeMaxDynamicSharedMemorySize, GSM32);
    cudaFuncSetAttribute(gemm_fp16<3,32>,  cudaFuncAttributeMaxDynamicSharedMemorySize, GSM32);
    cudaFuncSetAttribute(gemm_fp16<6,32>,  cudaFuncAttributeMaxDynamicSharedMemorySize, GSM32);
    cudaFuncSetAttribute(gemm_fp16<1,128>, cudaFuncAttributeMaxDynamicSharedMemorySize, GSM128);
    cudaFuncSetAttribute(gemm_fp16<2,128>, cudaFuncAttributeMaxDynamicSharedMemorySize, GSM128);
    cudaFuncSetAttribute(gemm_fp16<5,128>, cudaFuncAttributeMaxDynamicSharedMemorySize, GSM128);
    cudaFuncSetAttribute(fused_attn, cudaFuncAttributeMaxDynamicSharedMemorySize, FA_SMEM);

    // #1: merged prolog (all transposes + patchify + time-embed)
    prolog_k<<<PROLOG_BLOCKS, 256>>>(x, convw, convb, tok, tt, c0,
        qkvw, qkvwT, ow, owT, aw, awT, m1w, m1wT, m2w, m2wT,
        tw1, tw1T, tw2, tw2T, faw, fawT);

    // conditioning on M=32 tiles (silu fused into tmlp2 epilogue)
    gemm_fp16<3,32><<<dim3(HID/128, 1, 1), 256, GSM32>>>(c0, DD, tw1T, tb1,
        nullptr, tmid, 32, HID, DD, nullptr, 0, nullptr, 0, 0, 0);
    gemm_fp16<6,32><<<dim3(DD/128, 1, 1), 256, GSM32>>>(tmid, HID, tw2T, tb2,
        nullptr, sc, 32, DD, HID, cls, 0, lab, 0, 0, 0);
    gemm_fp16<0,32><<<dim3(6*DD/128, 1, LL), 256, GSM32>>>(sc, DD, awT, ab,
        ada, nullptr, 32, 6*DD, DD, nullptr, 0, nullptr,
        (long long)6*DD*DD, (long long)6*DD, (long long)BB*6*DD);

    ln_mod_k<<<TT, 192>>>(tok, ada, 6*DD, 0, DD, hmod);
    for (int i = 0; i < LL; i++){
        const float* adaL = ada + (size_t)i*BB*6*DD;
        gemm_fp16<5,128><<<dim3(3*DD/128, TT/128, 1), 256, GSM128>>>(hmod, DD,
            qkvwT + (size_t)i*3*DD*DD, qkvb + (size_t)i*3*DD,
            nullptr, qkv, TT, 3*DD, DD, nullptr, 0, nullptr, 0, 0, 0);
        fused_attn<<<dim3(2, BHH), 256, FA_SMEM>>>(qkv, oo);
        gemm_fp16<2,128><<<dim3(DD/128, TT/128, 1), 256, GSM128>>>(oo, DD,
            owT + (size_t)i*DD*DD, ob + (size_t)i*DD,
            tok, nullptr, TT, DD, DD, adaL, 2*DD, nullptr, 0, 0, 0);
        // mlp branch
        ln_mod_k<<<TT, 192>>>(tok, adaL, 6*DD, 3*DD, 4*DD, hmod);
        gemm_fp16<1,128><<<dim3(HID/128, TT/128, 1), 256, GSM128>>>(hmod, DD,
            m1wT + (size_t)i*HID*DD, m1b + (size_t)i*HID,
            nullptr, hmid, TT, HID, DD, nullptr, 0, nullptr, 0, 0, 0);
        gemm_fp16<2,128><<<dim3(DD/128, TT/128, 1), 256, GSM128>>>(hmid, HID,
            m2wT + (size_t)i*DD*HID, m2b + (size_t)i*DD,
            tok, nullptr, TT, DD, HID, adaL, 5*DD, nullptr, 0, 0, 0);
        if (i + 1 < LL)
            ln_mod_k<<<TT, 192>>>(tok, ada + (size_t)(i+1)*BB*6*DD, 6*DD, 0, DD, hmod);
    }

    gemm_fp16<0,32><<<dim3(2*DD/128, 1, 1), 256, GSM32>>>(sc, DD, fawT, fab,
        adaf, nullptr, 32, 2*DD, DD, nullptr, 0, nullptr, 0, 0, 0);
    ln_mod_k<<<TT, 192>>>(tok, adaf, 2*DD, 0, DD, hmod);
    final_k<<<TT, 128>>>(hmod, flw, flb, out);
}